// round 6
// baseline (speedup 1.0000x reference)
#include <cuda_runtime.h>
#include <cuda_bf16.h>
#include <cstdint>

#define BATCH 32
#define LEN   512
#define DIM   384                 // floats per row
#define ROW_BYTES (DIM * 4)       // 1536
#define ROW_F4    (DIM / 4)       // 96
#define NPOS  16                  // x values in [0,16) -> pos in [0,16)
#define THREADS 512
#define EMIT_CHUNKS 8             // 8 chunks x 64 tokens = 512 tokens
#define TOK_PER_CHUNK (LEN / EMIT_CHUNKS)
#define ZROWS 8                   // zero rows per tail bulk (12KB)
#define ZROWS_PER_CHUNK (128 * ZROWS)   // 1024 rows per zero-chunk CTA

__device__ __forceinline__ uint32_t smem_u32(const void* p) {
    uint32_t a;
    asm("{ .reg .u64 t; cvta.to.shared.u64 t, %1; cvt.u32.u64 %0, t; }"
        : "=r"(a) : "l"(p));
    return a;
}

// Token-run emitter: the output rows of one token are pos_enc[0 : x_j),
// contiguous in both source (smem table) and destination. One bulk copy
// per TOKEN (~12KB avg) instead of one per timestep (1.5KB): 8x fewer
// TMA requests. Tail [total, T) is zero-filled with 12KB zero-bulks.
__global__ void __launch_bounds__(THREADS)
emit_kernel(const int* __restrict__ x, const float* __restrict__ pe,
            float* __restrict__ out, int T) {
    __shared__ __align__(16) float4 s_pe[NPOS * ROW_F4];     // 24KB
    __shared__ __align__(16) float4 s_zero[ZROWS * ROW_F4];  // 12KB
    __shared__ int s_cs[LEN];
    __shared__ int s_wsum[16];

    const int b    = blockIdx.y;
    const int tid  = threadIdx.x;
    const int lane = tid & 31;
    const int warp = tid >> 5;
    const bool is_emit = (blockIdx.x < EMIT_CHUNKS);

    // ---- stage smem sources ----
    if (is_emit) {
        const float4* pe4 = reinterpret_cast<const float4*>(pe);
#pragma unroll
        for (int i = tid; i < NPOS * ROW_F4; i += THREADS)
            s_pe[i] = pe4[i];
    } else {
#pragma unroll
        for (int i = tid; i < ZROWS * ROW_F4; i += THREADS)
            s_zero[i] = make_float4(0.f, 0.f, 0.f, 0.f);
    }

    // ---- inclusive scan of x[b, :] (warp shuffle scan, 512 elems) ----
    int v = x[b * LEN + tid];
#pragma unroll
    for (int o = 1; o < 32; o <<= 1) {
        int n = __shfl_up_sync(0xFFFFFFFFu, v, o);
        if (lane >= o) v += n;
    }
    if (lane == 31) s_wsum[warp] = v;
    __syncthreads();
    if (warp == 0 && lane < 16) {
        int w = s_wsum[lane];
#pragma unroll
        for (int o = 1; o < 16; o <<= 1) {
            int n = __shfl_up_sync(0x0000FFFFu, w, o);
            if (lane >= o) w += n;
        }
        s_wsum[lane] = w;
    }
    __syncthreads();
    const int woff = (warp > 0) ? s_wsum[warp - 1] : 0;
    const int cs   = v + woff;                 // inclusive cumsum at this tid
    s_cs[tid] = cs;
    __syncthreads();

    const int total = s_cs[LEN - 1];

    // Order generic-proxy smem writes before async-proxy TMA reads.
    asm volatile("fence.proxy.async.shared::cta;" ::: "memory");

    const float* base = out + (size_t)b * (size_t)T * DIM;

    if (is_emit) {
        // One bulk per token: rows [start, start+cnt) <- pe rows [0, cnt).
        const int tok = blockIdx.x * TOK_PER_CHUNK + (tid & (TOK_PER_CHUNK - 1));
        if (tid < TOK_PER_CHUNK) {
            const int end   = s_cs[tok];
            const int start = (tok > 0) ? s_cs[tok - 1] : 0;
            const int cnt   = end - start;     // = x[b][tok], in [0,16)
            if (cnt > 0) {
                float* gdst = (float*)base + (size_t)start * DIM;
                uint32_t src = smem_u32(&s_pe[0]);
                const unsigned bytes = (unsigned)cnt * ROW_BYTES;
                asm volatile(
                    "cp.async.bulk.global.shared::cta.bulk_group [%0], [%1], %2;"
                    :: "l"(gdst), "r"(src), "r"(bytes) : "memory");
            }
        }
    } else {
        // Zero-fill tail rows [total, T) in 12KB chunks.
        const int zc = blockIdx.x - EMIT_CHUNKS;
        if (tid < 128) {
            const int r0 = zc * ZROWS_PER_CHUNK + tid * ZROWS;
            const int lo = (r0 > total) ? r0 : total;
            const int hi = ((r0 + ZROWS) < T) ? (r0 + ZROWS) : T;
            if (lo < hi) {
                float* gdst = (float*)base + (size_t)lo * DIM;
                uint32_t src = smem_u32(&s_zero[0]);
                const unsigned bytes = (unsigned)(hi - lo) * ROW_BYTES;
                asm volatile(
                    "cp.async.bulk.global.shared::cta.bulk_group [%0], [%1], %2;"
                    :: "l"(gdst), "r"(src), "r"(bytes) : "memory");
            }
        }
    }
    asm volatile("cp.async.bulk.commit_group;" ::: "memory");
    // Keep smem alive until the TMA engine has read it.
    asm volatile("cp.async.bulk.wait_group 0;" ::: "memory");
}

extern "C" void kernel_launch(void* const* d_in, const int* in_sizes, int n_in,
                              void* d_out, int out_size) {
    const int*   x;
    const float* pe;
    if (in_sizes[0] == BATCH * LEN) {
        x  = (const int*)d_in[0];
        pe = (const float*)d_in[1];
    } else {
        x  = (const int*)d_in[1];
        pe = (const float*)d_in[0];
    }

    const int T = out_size / (BATCH * DIM);
    float* out = (float*)d_out;

    const int zero_chunks = (T + ZROWS_PER_CHUNK - 1) / ZROWS_PER_CHUNK;
    dim3 grid(EMIT_CHUNKS + zero_chunks, BATCH);
    emit_kernel<<<grid, THREADS>>>(x, pe, out, T);
}

// round 7
// speedup vs baseline: 1.2740x; 1.2740x over previous
#include <cuda_runtime.h>
#include <cuda_bf16.h>
#include <cstdint>

#define BATCH 32
#define LEN   512
#define DIM   384                 // floats per row
#define ROW_BYTES (DIM * 4)       // 1536
#define ROW_F4    (DIM / 4)       // 96
#define NPOS  16                  // x values in [0,16) -> pos in [0,16)
#define T_PER_BLOCK 128
#define THREADS 512

__device__ __forceinline__ uint32_t smem_u32(const void* p) {
    uint32_t a;
    asm("{ .reg .u64 t; cvta.to.shared.u64 t, %1; cvt.u32.u64 %0, t; }"
        : "=r"(a) : "l"(p));
    return a;
}

__device__ __forceinline__ int search_row(const int* s_cs, int t, int total) {
    if (t >= total) return NPOS;          // zero row
    int lo = 0, hi = LEN;                 // searchsorted(cs, t, 'right')
    while (lo < hi) {
        int mid = (lo + hi) >> 1;
        if (s_cs[mid] > t) hi = mid; else lo = mid + 1;
    }
    const int start = (lo > 0) ? s_cs[lo - 1] : 0;
    return t - start;                     // < 16 since x values < 16
}

// Hybrid dual-path writer: even blocks push their 128 rows through the
// STG (L1->LTS) write path, odd blocks through the TMA bulk path. If the
// two paths have independent write-queue limits, aggregate write BW
// exceeds the ~4.1 TB/s single-path ceiling.
__global__ void __launch_bounds__(THREADS)
emit_kernel(const int* __restrict__ x, const float* __restrict__ pe,
            float* __restrict__ out, int T) {
    // Rows 0..15 = pos_enc[0..15], row 16 = zeros.
    __shared__ __align__(16) float4 s_pe[(NPOS + 1) * ROW_F4];
    __shared__ int s_cs[LEN];
    __shared__ int s_wsum[16];

    const int b    = blockIdx.y;
    const int tid  = threadIdx.x;
    const int lane = tid & 31;
    const int warp = tid >> 5;

    // ---- stage table ----
    const float4* pe4 = reinterpret_cast<const float4*>(pe);
#pragma unroll
    for (int i = tid; i < NPOS * ROW_F4; i += THREADS)
        s_pe[i] = pe4[i];
    if (tid < ROW_F4)
        s_pe[NPOS * ROW_F4 + tid] = make_float4(0.f, 0.f, 0.f, 0.f);

    // ---- inclusive scan of x[b, :] ----
    int v = x[b * LEN + tid];
#pragma unroll
    for (int o = 1; o < 32; o <<= 1) {
        int n = __shfl_up_sync(0xFFFFFFFFu, v, o);
        if (lane >= o) v += n;
    }
    if (lane == 31) s_wsum[warp] = v;
    __syncthreads();
    if (warp == 0 && lane < 16) {
        int w = s_wsum[lane];
#pragma unroll
        for (int o = 1; o < 16; o <<= 1) {
            int n = __shfl_up_sync(0x0000FFFFu, w, o);
            if (lane >= o) w += n;
        }
        s_wsum[lane] = w;
    }
    __syncthreads();
    const int woff = (warp > 0) ? s_wsum[warp - 1] : 0;
    s_cs[tid] = v + woff;
    __syncthreads();

    const int total = s_cs[LEN - 1];
    const int tbase = blockIdx.x * T_PER_BLOCK;

    if (blockIdx.x & 1) {
        // ---- TMA path: one thread per row, 1536B bulk from smem ----
        const int t = tbase + tid;
        if (tid < T_PER_BLOCK && t < T) {
            const int row = search_row(s_cs, t, total);
            asm volatile("fence.proxy.async.shared::cta;" ::: "memory");
            float* gdst = out + ((size_t)b * T + t) * DIM;
            uint32_t src = smem_u32(&s_pe[row * ROW_F4]);
            asm volatile(
                "cp.async.bulk.global.shared::cta.bulk_group [%0], [%1], %2;"
                :: "l"(gdst), "r"(src), "r"(ROW_BYTES) : "memory");
        }
        asm volatile("cp.async.bulk.commit_group;" ::: "memory");
        asm volatile("cp.async.bulk.wait_group 0;" ::: "memory");
    } else {
        // ---- STG path: warp per row (8 rows/warp), 3x STG.128/lane ----
        float4* out4 = reinterpret_cast<float4*>(out);
#pragma unroll
        for (int i = 0; i < T_PER_BLOCK / 16; ++i) {   // 8 rows per warp
            const int t = tbase + warp * (T_PER_BLOCK / 16) + i;
            if (t >= T) break;
            const int row = search_row(s_cs, t, total);
            const float4* src = &s_pe[row * ROW_F4];
            float4* dst = out4 + ((size_t)b * T + t) * ROW_F4;
            float4 v0 = src[lane];
            float4 v1 = src[lane + 32];
            float4 v2 = src[lane + 64];
            dst[lane]      = v0;
            dst[lane + 32] = v1;
            dst[lane + 64] = v2;
        }
    }
}

extern "C" void kernel_launch(void* const* d_in, const int* in_sizes, int n_in,
                              void* d_out, int out_size) {
    const int*   x;
    const float* pe;
    if (in_sizes[0] == BATCH * LEN) {
        x  = (const int*)d_in[0];
        pe = (const float*)d_in[1];
    } else {
        x  = (const int*)d_in[1];
        pe = (const float*)d_in[0];
    }

    const int T = out_size / (BATCH * DIM);
    float* out = (float*)d_out;

    dim3 grid((T + T_PER_BLOCK - 1) / T_PER_BLOCK, BATCH);
    emit_kernel<<<grid, THREADS>>>(x, pe, out, T);
}